// round 2
// baseline (speedup 1.0000x reference)
#include <cuda_runtime.h>
#include <cuda_bf16.h>

#define NB 2
#define NC 64
#define NTOK (64*64*64)                 // 262144 tokens per batch
#define NHEADS 4
#define DH 32
#define GRAM_CHUNKS 256
#define TOK_PER_CTA (NTOK / GRAM_CHUNKS) // 1024
#define TILE_T 64
#define XS_STRIDE 68                     // 64 + 4 pad: 16B-aligned rows, conflict-light

// ---------------- static device scratch (no allocations) ----------------
__device__ float g_Gpart[NB][GRAM_CHUNKS][NC * NC]; // 8 MB partial Grams
__device__ float g_G[NB][NC * NC];                  // reduced Gram
__device__ float g_Mpart[NB][NHEADS][NC * NC];      // per-head M contrib, [c*64+o]
__device__ float g_Mt[NB][NC * NC];                 // final M transposed: [c][o]

typedef unsigned long long ull;

__device__ __forceinline__ ull ffma2(ull a, ull b, ull c) {
    ull d;
    asm("fma.rn.f32x2 %0, %1, %2, %3;" : "=l"(d) : "l"(a), "l"(b), "l"(c));
    return d;
}
__device__ __forceinline__ ull pack2(float x, float y) {
    ull d;
    asm("mov.b64 %0, {%1, %2};" : "=l"(d) : "f"(x), "f"(y));
    return d;
}
__device__ __forceinline__ float2 unpack2(ull v) {
    float2 r;
    asm("mov.b64 {%0, %1}, %2;" : "=f"(r.x), "=f"(r.y) : "l"(v));
    return r;
}

// ============ Kernel 1: partial Gram  G = sum_n x[:,n] x[:,n]^T ============
// 256 threads; thread (bi,bj) owns G rows 4bi..4bi+3 x cols 4bj..4bj+3.
__global__ __launch_bounds__(256) void gram_kernel(const float* __restrict__ x) {
    __shared__ float Xs[TILE_T * XS_STRIDE];    // [t][c], padded
    const int b = blockIdx.y;
    const int tid = threadIdx.x;
    const int bi = tid >> 4;     // row chunk (4 rows)
    const int bj = tid & 15;     // col chunk (4 cols)
    const float* xb = x + (size_t)b * NC * NTOK + (size_t)blockIdx.x * TOK_PER_CTA;

    ull acc[2][4];
#pragma unroll
    for (int i = 0; i < 2; i++)
#pragma unroll
        for (int j = 0; j < 4; j++) acc[i][j] = 0ULL;

    for (int tt = 0; tt < TOK_PER_CTA; tt += TILE_T) {
        __syncthreads();
#pragma unroll
        for (int k = 0; k < 16; k++) {
            int idx = tid + k * 256;
            int c = idx >> 6, t = idx & 63;
            Xs[t * XS_STRIDE + c] = xb[(size_t)c * NTOK + tt + t];  // coalesced gmem
        }
        __syncthreads();
#pragma unroll 16
        for (int t = 0; t < TILE_T; t++) {
            float4 av = *(const float4*)&Xs[t * XS_STRIDE + 4 * bi];
            float4 bv = *(const float4*)&Xs[t * XS_STRIDE + 4 * bj];
            ull a01 = pack2(av.x, av.y);
            ull a23 = pack2(av.z, av.w);
            ull b0 = pack2(bv.x, bv.x);
            ull b1 = pack2(bv.y, bv.y);
            ull b2 = pack2(bv.z, bv.z);
            ull b3 = pack2(bv.w, bv.w);
            acc[0][0] = ffma2(a01, b0, acc[0][0]);
            acc[1][0] = ffma2(a23, b0, acc[1][0]);
            acc[0][1] = ffma2(a01, b1, acc[0][1]);
            acc[1][1] = ffma2(a23, b1, acc[1][1]);
            acc[0][2] = ffma2(a01, b2, acc[0][2]);
            acc[1][2] = ffma2(a23, b2, acc[1][2]);
            acc[0][3] = ffma2(a01, b3, acc[0][3]);
            acc[1][3] = ffma2(a23, b3, acc[1][3]);
        }
    }
    float* dst = g_Gpart[b][blockIdx.x];
#pragma unroll
    for (int i2 = 0; i2 < 2; i2++)
#pragma unroll
        for (int j = 0; j < 4; j++) {
            float2 f = unpack2(acc[i2][j]);
            int row0 = 4 * bi + 2 * i2;
            int col = 4 * bj + j;
            dst[row0 * 64 + col] = f.x;
            dst[(row0 + 1) * 64 + col] = f.y;
        }
}

// ============ Kernel 2: deterministic reduce of Gram partials ============
__global__ void reduce_g() {
    int idx = blockIdx.x * blockDim.x + threadIdx.x;   // 8192 threads
    int b = idx >> 12, e = idx & 4095;
    float s0 = 0.f, s1 = 0.f, s2 = 0.f, s3 = 0.f;
    for (int k = 0; k < GRAM_CHUNKS; k += 4) {
        s0 += g_Gpart[b][k + 0][e];
        s1 += g_Gpart[b][k + 1][e];
        s2 += g_Gpart[b][k + 2][e];
        s3 += g_Gpart[b][k + 3][e];
    }
    g_G[b][e] = (s0 + s1) + (s2 + s3);
}

// ======== Kernel 3: M_h = scale * Wout_h (Wk_h G Wv_h^T / 4096)^T Wq_h ========
// One CTA per (head, batch). Weights & G read through L1; intermediates in smem.
__global__ __launch_bounds__(256) void combine_kernel(const float* __restrict__ w_qkv,
                                                      const float* __restrict__ w_out) {
    __shared__ float T1[64 * 32];   // (G Wv^T)[c1][e]
    __shared__ float CT[32 * 32];   // ctx[d][e]
    __shared__ float Am[32 * 64];   // A[e][c] = scale * (ctx^T Wq)[e][c]

    const int h = blockIdx.x, b = blockIdx.y;
    const int tid = threadIdx.x;
    const float* Wq = w_qkv + (h * DH) * 64;          // [d][c]
    const float* Wk = w_qkv + (128 + h * DH) * 64;    // [d][c]
    const float* Wv = w_qkv + (256 + h * DH) * 64;    // [e][c]
    const float* G  = g_G[b];

    // Phase 1: T1[c1][e] = sum_c2 G[c1][c2] * Wv[e][c2]
    {
        int base = tid * 8;
        int c1 = base >> 5, e0 = base & 31;   // e0 in {0,8,16,24}
        float a[8] = {0, 0, 0, 0, 0, 0, 0, 0};
        for (int c2 = 0; c2 < 64; c2++) {
            float gv = __ldg(&G[c1 * 64 + c2]);
#pragma unroll
            for (int r = 0; r < 8; r++) a[r] += gv * __ldg(&Wv[(e0 + r) * 64 + c2]);
        }
#pragma unroll
        for (int r = 0; r < 8; r++) T1[c1 * 32 + e0 + r] = a[r];
    }
    __syncthreads();

    // Phase 2: CT[d][e] = (1/4096) * sum_c1 Wk[d][c1] * T1[c1][e]
    {
        int base = tid * 4;
        int d = base >> 5, e0 = base & 31;    // e0 in {0,4,...,28}
        float a[4] = {0, 0, 0, 0};
        for (int c1 = 0; c1 < 64; c1++) {
            float wk = __ldg(&Wk[d * 64 + c1]);
#pragma unroll
            for (int r = 0; r < 4; r++) a[r] += wk * T1[c1 * 32 + e0 + r];
        }
#pragma unroll
        for (int r = 0; r < 4; r++) CT[d * 32 + e0 + r] = a[r] * (1.0f / 4096.0f);
    }
    __syncthreads();

    // Phase 3: Am[e][c] = scale * sum_d CT[d][e] * Wq[d][c]
    {
        int base = tid * 8;
        int e = base >> 6, c0 = base & 63;    // c0 in {0,8,...,56}
        float a[8] = {0, 0, 0, 0, 0, 0, 0, 0};
        for (int d = 0; d < 32; d++) {
            float cv = CT[d * 32 + e];
#pragma unroll
            for (int r = 0; r < 8; r++) a[r] += cv * __ldg(&Wq[d * 64 + c0 + r]);
        }
        const float scale = 0.17677669529663687f;   // 32^-0.5
#pragma unroll
        for (int r = 0; r < 8; r++) Am[e * 64 + c0 + r] = a[r] * scale;
    }
    __syncthreads();

    // Phase 4: Mpart[c][o] = sum_e Wout[o][h*32+e] * Am[e][c]   (stored transposed)
    {
        int o = tid >> 2, c0 = (tid & 3) * 16;
        float a[16];
#pragma unroll
        for (int r = 0; r < 16; r++) a[r] = 0.f;
        for (int e = 0; e < 32; e++) {
            float wo = __ldg(&w_out[o * 128 + h * DH + e]);
#pragma unroll
            for (int r = 0; r < 16; r++) a[r] += wo * Am[e * 64 + c0 + r];
        }
#pragma unroll
        for (int r = 0; r < 16; r++) g_Mpart[b][h][(c0 + r) * 64 + o] = a[r];
    }
}

// ============ Kernel 4: deterministic head reduce ============
__global__ void reduce_m() {
    int idx = blockIdx.x * blockDim.x + threadIdx.x;   // 8192 threads
    int b = idx >> 12, e = idx & 4095;
    g_Mt[b][e] = (g_Mpart[b][0][e] + g_Mpart[b][1][e]) +
                 (g_Mpart[b][2][e] + g_Mpart[b][3][e]);
}

// ======== Kernel 5: y = M x + b_out, then LayerNorm over channels ========
// 64-token tile per CTA. Token-pair FFMA2: acc[i][jp] = y[o=4bi+i][t=4bj+2jp+{0,1}]
__global__ __launch_bounds__(256) void apply_kernel(const float* __restrict__ x,
                                                    const float* __restrict__ b_out,
                                                    const float* __restrict__ gain,
                                                    float* __restrict__ out) {
    __shared__ float Ms[4096];                 // [c][o]  (M transposed)
    __shared__ float pool[64 * 66];            // Xs [c][t] (GEMM) -> Ys [t][o] s66 (epi)
    __shared__ float redS[256], redSS[256];
    __shared__ float stat_mu[64], stat_rs[64];
    __shared__ float bS[64], gS[64];

    const int b = blockIdx.y;
    const int tid = threadIdx.x;
    const int bi = tid >> 4;                   // output-channel chunk (4)
    const int bj = tid & 15;                   // token chunk (4)
    const size_t tbase = (size_t)blockIdx.x * 64;
    const float* xb = x + (size_t)b * NC * NTOK + tbase;

#pragma unroll
    for (int k = 0; k < 16; k++) {
        int idx = tid + k * 256;
        Ms[idx] = g_Mt[b][idx];
        int c = idx >> 6, t = idx & 63;
        pool[idx] = xb[(size_t)c * NTOK + t];  // [c][t], coalesced, conflict-free
    }
    if (tid < 64) { bS[tid] = b_out[tid]; gS[tid] = gain[tid]; }
    __syncthreads();

    ull acc[4][2];
#pragma unroll
    for (int i = 0; i < 4; i++) { acc[i][0] = 0ULL; acc[i][1] = 0ULL; }

#pragma unroll 8
    for (int c = 0; c < 64; c++) {
        float4 mv = *(const float4*)&Ms[c * 64 + 4 * bi];     // broadcast
        float4 xv = *(const float4*)&pool[c * 64 + 4 * bj];   // 4 tokens
        ull xpa = pack2(xv.x, xv.y);     // token pair 0 (natural pair)
        ull xpb = pack2(xv.z, xv.w);     // token pair 1
        ull m0 = pack2(mv.x, mv.x);
        ull m1 = pack2(mv.y, mv.y);
        ull m2 = pack2(mv.z, mv.z);
        ull m3 = pack2(mv.w, mv.w);
        acc[0][0] = ffma2(m0, xpa, acc[0][0]);
        acc[0][1] = ffma2(m0, xpb, acc[0][1]);
        acc[1][0] = ffma2(m1, xpa, acc[1][0]);
        acc[1][1] = ffma2(m1, xpb, acc[1][1]);
        acc[2][0] = ffma2(m2, xpa, acc[2][0]);
        acc[2][1] = ffma2(m2, xpb, acc[2][1]);
        acc[3][0] = ffma2(m3, xpa, acc[3][0]);
        acc[3][1] = ffma2(m3, xpb, acc[3][1]);
    }
    __syncthreads();   // all pool reads done; reuse as Ys

    // Ys[t][o], stride 66: y + bias
#pragma unroll
    for (int i = 0; i < 4; i++) {
        int o = 4 * bi + i;
        float bo = bS[o];
#pragma unroll
        for (int jp = 0; jp < 2; jp++) {
            float2 f = unpack2(acc[i][jp]);
            int t0 = 4 * bj + 2 * jp;
            pool[t0 * 66 + o] = f.x + bo;
            pool[(t0 + 1) * 66 + o] = f.y + bo;
        }
    }
    __syncthreads();

    // per-token mean/var: 4 threads per token, 16 channels each
    {
        int t = tid >> 2, q = tid & 3;
        float s = 0.f, ss = 0.f;
#pragma unroll
        for (int k = 0; k < 16; k++) {
            float v = pool[t * 66 + 16 * q + k];
            s += v; ss += v * v;
        }
        redS[tid] = s; redSS[tid] = ss;
    }
    __syncthreads();
    if (tid < 64) {
        float S  = (redS[tid * 4] + redS[tid * 4 + 1]) + (redS[tid * 4 + 2] + redS[tid * 4 + 3]);
        float SS = (redSS[tid * 4] + redSS[tid * 4 + 1]) + (redSS[tid * 4 + 2] + redSS[tid * 4 + 3]);
        float mu = S * (1.0f / 64.0f);
        float var = SS * (1.0f / 64.0f) - mu * mu;
        stat_mu[tid] = mu;
        stat_rs[tid] = rsqrtf(var + 1e-5f);
    }
    __syncthreads();

    // normalize + gain, coalesced store
    float* ob = out + (size_t)b * NC * NTOK + tbase;
#pragma unroll
    for (int k = 0; k < 16; k++) {
        int idx = tid + k * 256;
        int c = idx >> 6, t = idx & 63;
        float v = (pool[t * 66 + c] - stat_mu[t]) * stat_rs[t] * gS[c];
        ob[(size_t)c * NTOK + t] = v;
    }
}

extern "C" void kernel_launch(void* const* d_in, const int* in_sizes, int n_in,
                              void* d_out, int out_size) {
    const float* x     = (const float*)d_in[0];   // [2,64,64,64,64]
    const float* w_qkv = (const float*)d_in[1];   // [384,64]
    const float* w_out = (const float*)d_in[2];   // [64,128]
    const float* b_out = (const float*)d_in[3];   // [64]
    const float* g     = (const float*)d_in[4];   // [64]
    float* out = (float*)d_out;

    gram_kernel<<<dim3(GRAM_CHUNKS, NB), 256>>>(x);
    reduce_g<<<32, 256>>>();
    combine_kernel<<<dim3(NHEADS, NB), 256>>>(w_qkv, w_out);
    reduce_m<<<32, 256>>>();
    apply_kernel<<<dim3(NTOK / 64, NB), 256>>>(x, b_out, g, out);
}